// round 2
// baseline (speedup 1.0000x reference)
#include <cuda_runtime.h>
#include <cuda_bf16.h>
#include <cstdint>

#define N_NODES 100000
#define N_EDGES 600000
#define N_GRAPHS 64
#define BN_EPS 1e-5f

// ---------------- scratch (device globals; no allocation allowed) ----------------
__device__ float g_y[(size_t)N_NODES * 64];     // projected features y = x @ W1
__device__ float g_aggr[(size_t)N_NODES * 64];  // scatter accumulator
__device__ float g_a[(size_t)N_NODES * 64];     // layer output (64-dim)
__device__ float g_f[(size_t)N_NODES * 96];     // final layer output (96-dim)
__device__ float g_sums[N_GRAPHS * 96];
__device__ int   g_cnts[N_GRAPHS];
__device__ int   g_src[N_EDGES];
__device__ int   g_dst[N_EDGES];
__device__ int   g_batch32[N_NODES];
__device__ int   g_is64_ei;
__device__ int   g_is64_b;

// ---------------- dtype detection: int64 vs int32 index buffers ----------------
// If the buffer truly holds int64 values in [0, maxval), every 8-byte word is a
// small nonnegative number. If it holds int32s, the reinterpreted int64 combines
// two random values -> >= 2^32 with prob ~1 per element. Check 1024 samples.
__global__ void detect_kernel(const void* ei, int n64_check, int maxval, int* flag) {
    if (threadIdx.x == 0 && blockIdx.x == 0) {
        const long long* p = (const long long*)ei;
        int ok = 1;
        for (int i = 0; i < n64_check; i++) {
            long long v = p[i];
            if (v < 0 || v >= maxval) { ok = 0; break; }
        }
        *flag = ok;
    }
}

__global__ void convert_edges_kernel(const void* ei, const int* flag,
                                     int* __restrict__ src, int* __restrict__ dst) {
    int i = blockIdx.x * blockDim.x + threadIdx.x;
    if (i >= N_EDGES) return;
    if (*flag) {
        const long long* p = (const long long*)ei;
        src[i] = (int)p[i];
        dst[i] = (int)p[N_EDGES + i];
    } else {
        const int* p = (const int*)ei;
        src[i] = p[i];
        dst[i] = p[N_EDGES + i];
    }
}

__global__ void convert_batch_kernel(const void* b, const int* flag,
                                     int* __restrict__ out) {
    int i = blockIdx.x * blockDim.x + threadIdx.x;
    if (i >= N_NODES) return;
    if (*flag) out[i] = (int)((const long long*)b)[i];
    else       out[i] = ((const int*)b)[i];
}

// ---------------- GEMM1: Y[node,64] = X[node,K] @ W[K,64] ----------------
template <int K>
__global__ __launch_bounds__(128) void gemm1_kernel(const float* __restrict__ X,
                                                    const float* __restrict__ W,
                                                    float* __restrict__ Y) {
    extern __shared__ float sh[];
    float* Ws = sh;                 // K*64
    float* Xs = sh + K * 64;        // 128*(K+1)
    const int tid = threadIdx.x;
    const int base = blockIdx.x * 128;

    for (int i = tid; i < K * 16; i += 128)
        ((float4*)Ws)[i] = ((const float4*)W)[i];

    const int NT4 = 128 * K / 4;
    for (int i = tid; i < NT4; i += 128) {
        int lin = i * 4;
        int row = lin / K, col = lin % K;
        float4 v = make_float4(0.f, 0.f, 0.f, 0.f);
        if (base + row < N_NODES)
            v = *(const float4*)(X + (size_t)(base + row) * K + col);
        float* d = Xs + row * (K + 1) + col;
        d[0] = v.x; d[1] = v.y; d[2] = v.z; d[3] = v.w;
    }
    __syncthreads();

    const int node = base + tid;
    if (node >= N_NODES) return;

    float acc[64];
#pragma unroll
    for (int j = 0; j < 64; j++) acc[j] = 0.f;

    const float* xr = Xs + tid * (K + 1);
#pragma unroll 2
    for (int k = 0; k < K; k++) {
        float xv = xr[k];
        const float4* wr = (const float4*)(Ws + k * 64);
#pragma unroll
        for (int j4 = 0; j4 < 16; j4++) {
            float4 w = wr[j4];
            acc[j4 * 4 + 0] += xv * w.x;
            acc[j4 * 4 + 1] += xv * w.y;
            acc[j4 * 4 + 2] += xv * w.z;
            acc[j4 * 4 + 3] += xv * w.w;
        }
    }
    float* yo = Y + (size_t)node * 64;
#pragma unroll
    for (int j4 = 0; j4 < 16; j4++)
        ((float4*)yo)[j4] = make_float4(acc[j4 * 4], acc[j4 * 4 + 1],
                                        acc[j4 * 4 + 2], acc[j4 * 4 + 3]);
}

// ---------------- scatter: aggr[dst] += y[src] (64-dim), vector red ----------------
__global__ void scatter_kernel(const float* __restrict__ Y,
                               const int* __restrict__ src,
                               const int* __restrict__ dst,
                               float* __restrict__ A) {
    int idx = blockIdx.x * blockDim.x + threadIdx.x;   // N_EDGES*16 threads
    int e = idx >> 4;
    int g = idx & 15;
    if (e >= N_EDGES) return;
    int s = src[e];
    int d = dst[e];
    float4 v = *(const float4*)(Y + (size_t)s * 64 + g * 4);
    float* p = A + (size_t)d * 64 + g * 4;
    asm volatile("red.global.add.v4.f32 [%0], {%1,%2,%3,%4};"
                 :: "l"(p), "f"(v.x), "f"(v.y), "f"(v.z), "f"(v.w)
                 : "memory");
}

// ---------------- GEMM2: OUT = ReLU(BN( ReLU(y+aggr+b1) @ W2 + b2 )) ----------------
template <int NOUT>
__global__ __launch_bounds__(128) void gemm2_kernel(const float* __restrict__ Y,
                                                    const float* __restrict__ A,
                                                    const float* __restrict__ b1,
                                                    const float* __restrict__ W2,
                                                    const float* __restrict__ b2,
                                                    const float* __restrict__ bng,
                                                    const float* __restrict__ bnb,
                                                    const float* __restrict__ bnm,
                                                    const float* __restrict__ bnv,
                                                    float* __restrict__ OUT) {
    const int K = 64;
    extern __shared__ float sh[];
    float* Ws = sh;                 // K*NOUT
    float* Hs = sh + K * NOUT;      // 128*(K+1)
    __shared__ float sScale[NOUT];
    __shared__ float sShift[NOUT];

    const int tid = threadIdx.x;
    const int base = blockIdx.x * 128;

    if (tid < NOUT) {
        float s = bng[tid] * rsqrtf(bnv[tid] + BN_EPS);
        sScale[tid] = s;
        sShift[tid] = (b2[tid] - bnm[tid]) * s + bnb[tid];
    }

    for (int i = tid; i < K * NOUT / 4; i += 128)
        ((float4*)Ws)[i] = ((const float4*)W2)[i];

    const int NT4 = 128 * K / 4;
    for (int i = tid; i < NT4; i += 128) {
        int lin = i * 4;
        int row = lin / K, col = lin % K;
        float4 h = make_float4(0.f, 0.f, 0.f, 0.f);
        if (base + row < N_NODES) {
            size_t off = (size_t)(base + row) * K + col;
            float4 y = *(const float4*)(Y + off);
            float4 a = *(const float4*)(A + off);
            h.x = fmaxf(y.x + a.x + __ldg(b1 + col + 0), 0.f);
            h.y = fmaxf(y.y + a.y + __ldg(b1 + col + 1), 0.f);
            h.z = fmaxf(y.z + a.z + __ldg(b1 + col + 2), 0.f);
            h.w = fmaxf(y.w + a.w + __ldg(b1 + col + 3), 0.f);
        }
        float* d = Hs + row * (K + 1) + col;
        d[0] = h.x; d[1] = h.y; d[2] = h.z; d[3] = h.w;
    }
    __syncthreads();

    const int node = base + tid;
    if (node >= N_NODES) return;

    float acc[NOUT];
#pragma unroll
    for (int j = 0; j < NOUT; j++) acc[j] = 0.f;

    const float* xr = Hs + tid * (K + 1);
#pragma unroll 2
    for (int k = 0; k < K; k++) {
        float xv = xr[k];
        const float4* wr = (const float4*)(Ws + k * NOUT);
#pragma unroll
        for (int j4 = 0; j4 < NOUT / 4; j4++) {
            float4 w = wr[j4];
            acc[j4 * 4 + 0] += xv * w.x;
            acc[j4 * 4 + 1] += xv * w.y;
            acc[j4 * 4 + 2] += xv * w.z;
            acc[j4 * 4 + 3] += xv * w.w;
        }
    }

    float* oo = OUT + (size_t)node * NOUT;
#pragma unroll
    for (int j4 = 0; j4 < NOUT / 4; j4++) {
        float4 o;
        o.x = fmaxf(acc[j4 * 4 + 0] * sScale[j4 * 4 + 0] + sShift[j4 * 4 + 0], 0.f);
        o.y = fmaxf(acc[j4 * 4 + 1] * sScale[j4 * 4 + 1] + sShift[j4 * 4 + 1], 0.f);
        o.z = fmaxf(acc[j4 * 4 + 2] * sScale[j4 * 4 + 2] + sShift[j4 * 4 + 2], 0.f);
        o.w = fmaxf(acc[j4 * 4 + 3] * sScale[j4 * 4 + 3] + sShift[j4 * 4 + 3], 0.f);
        ((float4*)oo)[j4] = o;
    }
}

// ---------------- pool: per-block run-length partial sums over sorted batch ----------------
#define PB_NODES 64
__global__ void pool_kernel(const float* __restrict__ F,
                            const int* __restrict__ batch,
                            float* __restrict__ sums, int* __restrict__ cnts) {
    __shared__ int sb[PB_NODES];
    const int start = blockIdx.x * PB_NODES;
    const int nn = min(PB_NODES, N_NODES - start);
    const int tid = threadIdx.x;   // blockDim = 96
    if (tid < nn) sb[tid] = batch[start + tid];
    __syncthreads();

    if (tid == 0) {
        int cur = sb[0], c = 0;
        for (int n = 0; n < nn; n++) {
            int g = sb[n];
            if (g != cur) { atomicAdd(&cnts[cur], c); cur = g; c = 0; }
            c++;
        }
        atomicAdd(&cnts[cur], c);
    }
    int cur = sb[0];
    float acc = 0.f;
    for (int n = 0; n < nn; n++) {
        int g = sb[n];
        float v = F[(size_t)(start + n) * 96 + tid];
        if (g != cur) { atomicAdd(&sums[cur * 96 + tid], acc); acc = 0.f; cur = g; }
        acc += v;
    }
    atomicAdd(&sums[cur * 96 + tid], acc);
}

__global__ void finalize_kernel(const float* __restrict__ sums,
                                const int* __restrict__ cnts,
                                float* __restrict__ out) {
    int i = blockIdx.x * blockDim.x + threadIdx.x;
    if (i >= N_GRAPHS * 96) return;
    float c = fmaxf((float)cnts[i / 96], 1.f);
    out[i] = sums[i] / c;
}

// ---------------- launch ----------------
extern "C" void kernel_launch(void* const* d_in, const int* in_sizes, int n_in,
                              void* d_out, int out_size) {
    const float* x     = (const float*)d_in[0];
    const void*  ei    = d_in[1];
    const void*  batch = d_in[2];

    const float* P[24];
    for (int i = 0; i < 24; i++) P[i] = (const float*)d_in[3 + i];

    float *y, *aggr, *a, *f, *sums;
    int *cnts, *src, *dst, *b32, *f_ei, *f_b;
    cudaGetSymbolAddress((void**)&y,    g_y);
    cudaGetSymbolAddress((void**)&aggr, g_aggr);
    cudaGetSymbolAddress((void**)&a,    g_a);
    cudaGetSymbolAddress((void**)&f,    g_f);
    cudaGetSymbolAddress((void**)&sums, g_sums);
    cudaGetSymbolAddress((void**)&cnts, g_cnts);
    cudaGetSymbolAddress((void**)&src,  g_src);
    cudaGetSymbolAddress((void**)&dst,  g_dst);
    cudaGetSymbolAddress((void**)&b32,  g_batch32);
    cudaGetSymbolAddress((void**)&f_ei, g_is64_ei);
    cudaGetSymbolAddress((void**)&f_b,  g_is64_b);

    const int SM1_128 = (128 * 64 + 128 * 129) * 4;   // 98816
    const int SM1_64  = (64 * 64 + 128 * 65) * 4;     // 49664
    const int SM2_64  = (64 * 64 + 128 * 65) * 4;     // 49664
    const int SM2_96  = (64 * 96 + 128 * 65) * 4;     // 57856

    cudaFuncSetAttribute((const void*)gemm1_kernel<128>, cudaFuncAttributeMaxDynamicSharedMemorySize, SM1_128);
    cudaFuncSetAttribute((const void*)gemm1_kernel<64>,  cudaFuncAttributeMaxDynamicSharedMemorySize, SM1_64);
    cudaFuncSetAttribute((const void*)gemm2_kernel<64>,  cudaFuncAttributeMaxDynamicSharedMemorySize, SM2_64);
    cudaFuncSetAttribute((const void*)gemm2_kernel<96>,  cudaFuncAttributeMaxDynamicSharedMemorySize, SM2_96);

    const int NB  = (N_NODES + 127) / 128;             // 782
    const int SCB = (N_EDGES * 16) / 256;              // 37500
    const size_t AGG_BYTES = (size_t)N_NODES * 64 * sizeof(float);

    // ---- normalize index dtypes (int64 or int32) into int32 scratch ----
    detect_kernel<<<1, 32>>>(ei, 1024, N_NODES, f_ei);
    detect_kernel<<<1, 32>>>(batch, 1024, N_GRAPHS, f_b);
    convert_edges_kernel<<<(N_EDGES + 255) / 256, 256>>>(ei, f_ei, src, dst);
    convert_batch_kernel<<<(N_NODES + 255) / 256, 256>>>(batch, f_b, b32);

    // ---- layer 0 (K=128) ----
    gemm1_kernel<128><<<NB, 128, SM1_128>>>(x, P[0], y);
    cudaMemsetAsync(aggr, 0, AGG_BYTES, 0);
    scatter_kernel<<<SCB, 256>>>(y, src, dst, aggr);
    gemm2_kernel<64><<<NB, 128, SM2_64>>>(y, aggr, P[1], P[2], P[3], P[4], P[5], P[6], P[7], a);

    // ---- layer 1 ----
    gemm1_kernel<64><<<NB, 128, SM1_64>>>(a, P[8], y);
    cudaMemsetAsync(aggr, 0, AGG_BYTES, 0);
    scatter_kernel<<<SCB, 256>>>(y, src, dst, aggr);
    gemm2_kernel<64><<<NB, 128, SM2_64>>>(y, aggr, P[9], P[10], P[11], P[12], P[13], P[14], P[15], a);

    // ---- layer 2 (out=96) ----
    gemm1_kernel<64><<<NB, 128, SM1_64>>>(a, P[16], y);
    cudaMemsetAsync(aggr, 0, AGG_BYTES, 0);
    scatter_kernel<<<SCB, 256>>>(y, src, dst, aggr);
    gemm2_kernel<96><<<NB, 128, SM2_96>>>(y, aggr, P[17], P[18], P[19], P[20], P[21], P[22], P[23], f);

    // ---- mean pool ----
    cudaMemsetAsync(sums, 0, N_GRAPHS * 96 * sizeof(float), 0);
    cudaMemsetAsync(cnts, 0, N_GRAPHS * sizeof(int), 0);
    pool_kernel<<<(N_NODES + PB_NODES - 1) / PB_NODES, 96>>>(f, b32, sums, cnts);
    finalize_kernel<<<(N_GRAPHS * 96 + 255) / 256, 256>>>(sums, cnts, (float*)d_out);
}

// round 3
// speedup vs baseline: 1.2330x; 1.2330x over previous
#include <cuda_runtime.h>
#include <cuda_bf16.h>
#include <cstdint>

#define N_NODES 100000
#define N_EDGES 600000
#define N_GRAPHS 64
#define BN_EPS 1e-5f
#define SCAN_BS 256
#define NB_SCAN ((N_NODES + SCAN_BS - 1) / SCAN_BS)   // 391

// ---------------- scratch (device globals; no allocation allowed) ----------------
__device__ float g_y[(size_t)N_NODES * 64];     // projected features y = x @ W1
__device__ float g_aggr[(size_t)N_NODES * 64];  // gather output: y[i] + sum_j y[j]
__device__ float g_a[(size_t)N_NODES * 64];     // layer output (64-dim)
__device__ float g_f[(size_t)N_NODES * 96];     // final layer output (96-dim)
__device__ float g_sums[N_GRAPHS * 96];
__device__ int   g_cnts[N_GRAPHS];
__device__ int   g_src[N_EDGES];
__device__ int   g_dst[N_EDGES];
__device__ int   g_batch32[N_NODES];
__device__ int   g_deg[N_NODES];
__device__ int   g_rowptr[N_NODES + 1];
__device__ int   g_cursor[N_NODES];
__device__ int   g_col[N_EDGES];
__device__ int   g_part[NB_SCAN];
__device__ int   g_poff[NB_SCAN];
__device__ int   g_is64_ei;
__device__ int   g_is64_b;

// ---------------- dtype detection: int64 vs int32 index buffers ----------------
// Sample 256 int64 words STRIDED across [0, n64_max). If buffer is genuinely
// int64, every word is in [0, maxval). If it's int32, reinterpreted words pick
// up a high half from the neighbor value -> out of range with prob ~1 somewhere
// in the strided sample set (covers the tail, where sorted batch values are 63).
__global__ void detect_kernel(const void* p, long long n64_max, int maxval, int* flag) {
    __shared__ int ok;
    if (threadIdx.x == 0) ok = 1;
    __syncthreads();
    long long idx = (long long)threadIdx.x * (n64_max - 1) / 255;  // 256 threads
    long long v = ((const long long*)p)[idx];
    if (v < 0 || v >= maxval) atomicAnd(&ok, 0);
    __syncthreads();
    if (threadIdx.x == 0) *flag = ok;
}

// convert edges to int32 AND histogram in-degree
__global__ void convert_hist_kernel(const void* ei, const int* flag,
                                    int* __restrict__ src, int* __restrict__ dst,
                                    int* __restrict__ deg) {
    int i = blockIdx.x * blockDim.x + threadIdx.x;
    if (i >= N_EDGES) return;
    int s, d;
    if (*flag) {
        const long long* p = (const long long*)ei;
        s = (int)p[i]; d = (int)p[N_EDGES + i];
    } else {
        const int* p = (const int*)ei;
        s = p[i]; d = p[N_EDGES + i];
    }
    src[i] = s; dst[i] = d;
    atomicAdd(&deg[d], 1);
}

__global__ void convert_batch_kernel(const void* b, const int* flag,
                                     int* __restrict__ out) {
    int i = blockIdx.x * blockDim.x + threadIdx.x;
    if (i >= N_NODES) return;
    if (*flag) out[i] = (int)((const long long*)b)[i];
    else       out[i] = ((const int*)b)[i];
}

// ---------------- exclusive scan of deg -> rowptr (3 kernels) ----------------
__global__ void partials_kernel(const int* __restrict__ deg, int* __restrict__ part) {
    __shared__ int sm[SCAN_BS];
    int i = blockIdx.x * SCAN_BS + threadIdx.x;
    sm[threadIdx.x] = (i < N_NODES) ? deg[i] : 0;
    __syncthreads();
#pragma unroll
    for (int s = SCAN_BS / 2; s > 0; s >>= 1) {
        if (threadIdx.x < s) sm[threadIdx.x] += sm[threadIdx.x + s];
        __syncthreads();
    }
    if (threadIdx.x == 0) part[blockIdx.x] = sm[0];
}

__global__ void scan_partials_kernel(const int* __restrict__ part, int* __restrict__ poff) {
    __shared__ int sm[NB_SCAN];
    int t = threadIdx.x;
    for (int i = t; i < NB_SCAN; i += blockDim.x) sm[i] = part[i];
    __syncthreads();
    if (t == 0) {
        int run = 0;
        for (int i = 0; i < NB_SCAN; i++) { int v = sm[i]; sm[i] = run; run += v; }
    }
    __syncthreads();
    for (int i = t; i < NB_SCAN; i += blockDim.x) poff[i] = sm[i];
}

__global__ void rowptr_kernel(const int* __restrict__ deg, const int* __restrict__ poff,
                              int* __restrict__ rowptr, int* __restrict__ cursor) {
    __shared__ int sm[SCAN_BS];
    int b = blockIdx.x, t = threadIdx.x;
    int i = b * SCAN_BS + t;
    int v = (i < N_NODES) ? deg[i] : 0;
    sm[t] = v;
    __syncthreads();
    // inclusive Hillis-Steele scan (in-place, double sync)
    for (int off = 1; off < SCAN_BS; off <<= 1) {
        int x = (t >= off) ? sm[t - off] : 0;
        __syncthreads();
        sm[t] += x;
        __syncthreads();
    }
    if (i < N_NODES) {
        int r = poff[b] + sm[t] - v;   // exclusive
        rowptr[i] = r;
        cursor[i] = r;
    }
    if (i == N_NODES - 1) rowptr[N_NODES] = poff[b] + sm[t];
}

__global__ void fill_kernel(const int* __restrict__ src, const int* __restrict__ dst,
                            int* __restrict__ cursor, int* __restrict__ col) {
    int e = blockIdx.x * blockDim.x + threadIdx.x;
    if (e >= N_EDGES) return;
    int d = dst[e];
    int pos = atomicAdd(&cursor[d], 1);
    col[pos] = src[e];
}

// ---------------- GEMM1: Y[node,64] = X[node,K] @ W[K,64] ----------------
template <int K>
__global__ __launch_bounds__(128) void gemm1_kernel(const float* __restrict__ X,
                                                    const float* __restrict__ W,
                                                    float* __restrict__ Y) {
    extern __shared__ float sh[];
    float* Ws = sh;                 // K*64
    float* Xs = sh + K * 64;        // 128*(K+1)
    const int tid = threadIdx.x;
    const int base = blockIdx.x * 128;

    for (int i = tid; i < K * 16; i += 128)
        ((float4*)Ws)[i] = ((const float4*)W)[i];

    const int NT4 = 128 * K / 4;
    for (int i = tid; i < NT4; i += 128) {
        int lin = i * 4;
        int row = lin / K, col = lin % K;
        float4 v = make_float4(0.f, 0.f, 0.f, 0.f);
        if (base + row < N_NODES)
            v = *(const float4*)(X + (size_t)(base + row) * K + col);
        float* d = Xs + row * (K + 1) + col;
        d[0] = v.x; d[1] = v.y; d[2] = v.z; d[3] = v.w;
    }
    __syncthreads();

    const int node = base + tid;
    if (node >= N_NODES) return;

    float acc[64];
#pragma unroll
    for (int j = 0; j < 64; j++) acc[j] = 0.f;

    const float* xr = Xs + tid * (K + 1);
#pragma unroll 2
    for (int k = 0; k < K; k++) {
        float xv = xr[k];
        const float4* wr = (const float4*)(Ws + k * 64);
#pragma unroll
        for (int j4 = 0; j4 < 16; j4++) {
            float4 w = wr[j4];
            acc[j4 * 4 + 0] += xv * w.x;
            acc[j4 * 4 + 1] += xv * w.y;
            acc[j4 * 4 + 2] += xv * w.z;
            acc[j4 * 4 + 3] += xv * w.w;
        }
    }
    float* yo = Y + (size_t)node * 64;
#pragma unroll
    for (int j4 = 0; j4 < 16; j4++)
        ((float4*)yo)[j4] = make_float4(acc[j4 * 4], acc[j4 * 4 + 1],
                                        acc[j4 * 4 + 2], acc[j4 * 4 + 3]);
}

// ---------------- gather: AG[i] = y[i] + sum_{e in CSR row i} y[col[e]] ----------------
// one warp per node, lane owns a float2 column (64 floats = 32 lanes x float2)
__global__ __launch_bounds__(256) void gather_kernel(const float* __restrict__ Y,
                                                     const int* __restrict__ rowptr,
                                                     const int* __restrict__ col,
                                                     float* __restrict__ AG) {
    int w = (blockIdx.x * blockDim.x + threadIdx.x) >> 5;
    int lane = threadIdx.x & 31;
    if (w >= N_NODES) return;
    const float2* y2 = (const float2*)Y;
    int r0 = rowptr[w], r1 = rowptr[w + 1];
    float2 acc = y2[(size_t)w * 32 + lane];
    int e = r0;
    for (; e + 1 < r1; e += 2) {
        int s0 = col[e];
        int s1 = col[e + 1];
        float2 a = y2[(size_t)s0 * 32 + lane];
        float2 b = y2[(size_t)s1 * 32 + lane];
        acc.x += a.x + b.x;
        acc.y += a.y + b.y;
    }
    if (e < r1) {
        int s = col[e];
        float2 a = y2[(size_t)s * 32 + lane];
        acc.x += a.x;
        acc.y += a.y;
    }
    ((float2*)AG)[(size_t)w * 32 + lane] = acc;
}

// ---------------- GEMM2: OUT = ReLU(BN( ReLU(AG+b1) @ W2 + b2 )) ----------------
template <int NOUT>
__global__ __launch_bounds__(128) void gemm2_kernel(const float* __restrict__ AG,
                                                    const float* __restrict__ b1,
                                                    const float* __restrict__ W2,
                                                    const float* __restrict__ b2,
                                                    const float* __restrict__ bng,
                                                    const float* __restrict__ bnb,
                                                    const float* __restrict__ bnm,
                                                    const float* __restrict__ bnv,
                                                    float* __restrict__ OUT) {
    const int K = 64;
    extern __shared__ float sh[];
    float* Ws = sh;                 // K*NOUT
    float* Hs = sh + K * NOUT;      // 128*(K+1)
    __shared__ float sScale[NOUT];
    __shared__ float sShift[NOUT];

    const int tid = threadIdx.x;
    const int base = blockIdx.x * 128;

    if (tid < NOUT) {
        float s = bng[tid] * rsqrtf(bnv[tid] + BN_EPS);
        sScale[tid] = s;
        sShift[tid] = (b2[tid] - bnm[tid]) * s + bnb[tid];
    }

    for (int i = tid; i < K * NOUT / 4; i += 128)
        ((float4*)Ws)[i] = ((const float4*)W2)[i];

    const int NT4 = 128 * K / 4;
    for (int i = tid; i < NT4; i += 128) {
        int lin = i * 4;
        int row = lin / K, col = lin % K;
        float4 h = make_float4(0.f, 0.f, 0.f, 0.f);
        if (base + row < N_NODES) {
            size_t off = (size_t)(base + row) * K + col;
            float4 a = *(const float4*)(AG + off);
            h.x = fmaxf(a.x + __ldg(b1 + col + 0), 0.f);
            h.y = fmaxf(a.y + __ldg(b1 + col + 1), 0.f);
            h.z = fmaxf(a.z + __ldg(b1 + col + 2), 0.f);
            h.w = fmaxf(a.w + __ldg(b1 + col + 3), 0.f);
        }
        float* d = Hs + row * (K + 1) + col;
        d[0] = h.x; d[1] = h.y; d[2] = h.z; d[3] = h.w;
    }
    __syncthreads();

    const int node = base + tid;
    if (node >= N_NODES) return;

    float acc[NOUT];
#pragma unroll
    for (int j = 0; j < NOUT; j++) acc[j] = 0.f;

    const float* xr = Hs + tid * (K + 1);
#pragma unroll 2
    for (int k = 0; k < K; k++) {
        float xv = xr[k];
        const float4* wr = (const float4*)(Ws + k * NOUT);
#pragma unroll
        for (int j4 = 0; j4 < NOUT / 4; j4++) {
            float4 w = wr[j4];
            acc[j4 * 4 + 0] += xv * w.x;
            acc[j4 * 4 + 1] += xv * w.y;
            acc[j4 * 4 + 2] += xv * w.z;
            acc[j4 * 4 + 3] += xv * w.w;
        }
    }

    float* oo = OUT + (size_t)node * NOUT;
#pragma unroll
    for (int j4 = 0; j4 < NOUT / 4; j4++) {
        float4 o;
        o.x = fmaxf(acc[j4 * 4 + 0] * sScale[j4 * 4 + 0] + sShift[j4 * 4 + 0], 0.f);
        o.y = fmaxf(acc[j4 * 4 + 1] * sScale[j4 * 4 + 1] + sShift[j4 * 4 + 1], 0.f);
        o.z = fmaxf(acc[j4 * 4 + 2] * sScale[j4 * 4 + 2] + sShift[j4 * 4 + 2], 0.f);
        o.w = fmaxf(acc[j4 * 4 + 3] * sScale[j4 * 4 + 3] + sShift[j4 * 4 + 3], 0.f);
        ((float4*)oo)[j4] = o;
    }
}

// ---------------- pool: per-block run-length partial sums over sorted batch ----------------
#define PB_NODES 64
__global__ void pool_kernel(const float* __restrict__ F,
                            const int* __restrict__ batch,
                            float* __restrict__ sums, int* __restrict__ cnts) {
    __shared__ int sb[PB_NODES];
    const int start = blockIdx.x * PB_NODES;
    const int nn = min(PB_NODES, N_NODES - start);
    const int tid = threadIdx.x;   // blockDim = 96
    if (tid < nn) sb[tid] = batch[start + tid];
    __syncthreads();

    if (tid == 0) {
        int cur = sb[0], c = 0;
        for (int n = 0; n < nn; n++) {
            int g = sb[n];
            if (g != cur) { atomicAdd(&cnts[cur], c); cur = g; c = 0; }
            c++;
        }
        atomicAdd(&cnts[cur], c);
    }
    int cur = sb[0];
    float acc = 0.f;
    for (int n = 0; n < nn; n++) {
        int g = sb[n];
        float v = F[(size_t)(start + n) * 96 + tid];
        if (g != cur) { atomicAdd(&sums[cur * 96 + tid], acc); acc = 0.f; cur = g; }
        acc += v;
    }
    atomicAdd(&sums[cur * 96 + tid], acc);
}

__global__ void finalize_kernel(const float* __restrict__ sums,
                                const int* __restrict__ cnts,
                                float* __restrict__ out) {
    int i = blockIdx.x * blockDim.x + threadIdx.x;
    if (i >= N_GRAPHS * 96) return;
    float c = fmaxf((float)cnts[i / 96], 1.f);
    out[i] = sums[i] / c;
}

// ---------------- launch ----------------
extern "C" void kernel_launch(void* const* d_in, const int* in_sizes, int n_in,
                              void* d_out, int out_size) {
    const float* x     = (const float*)d_in[0];
    const void*  ei    = d_in[1];
    const void*  batch = d_in[2];

    const float* P[24];
    for (int i = 0; i < 24; i++) P[i] = (const float*)d_in[3 + i];

    float *y, *aggr, *a, *f, *sums;
    int *cnts, *src, *dst, *b32, *f_ei, *f_b;
    int *deg, *rowptr, *cursor, *colv, *part, *poff;
    cudaGetSymbolAddress((void**)&y,      g_y);
    cudaGetSymbolAddress((void**)&aggr,   g_aggr);
    cudaGetSymbolAddress((void**)&a,      g_a);
    cudaGetSymbolAddress((void**)&f,      g_f);
    cudaGetSymbolAddress((void**)&sums,   g_sums);
    cudaGetSymbolAddress((void**)&cnts,   g_cnts);
    cudaGetSymbolAddress((void**)&src,    g_src);
    cudaGetSymbolAddress((void**)&dst,    g_dst);
    cudaGetSymbolAddress((void**)&b32,    g_batch32);
    cudaGetSymbolAddress((void**)&f_ei,   g_is64_ei);
    cudaGetSymbolAddress((void**)&f_b,    g_is64_b);
    cudaGetSymbolAddress((void**)&deg,    g_deg);
    cudaGetSymbolAddress((void**)&rowptr, g_rowptr);
    cudaGetSymbolAddress((void**)&cursor, g_cursor);
    cudaGetSymbolAddress((void**)&colv,   g_col);
    cudaGetSymbolAddress((void**)&part,   g_part);
    cudaGetSymbolAddress((void**)&poff,   g_poff);

    const int SM1_128 = (128 * 64 + 128 * 129) * 4;   // 98816
    const int SM1_64  = (64 * 64 + 128 * 65) * 4;     // 49664
    const int SM2_64  = (64 * 64 + 128 * 65) * 4;     // 49664
    const int SM2_96  = (64 * 96 + 128 * 65) * 4;     // 57856

    cudaFuncSetAttribute((const void*)gemm1_kernel<128>, cudaFuncAttributeMaxDynamicSharedMemorySize, SM1_128);
    cudaFuncSetAttribute((const void*)gemm1_kernel<64>,  cudaFuncAttributeMaxDynamicSharedMemorySize, SM1_64);
    cudaFuncSetAttribute((const void*)gemm2_kernel<64>,  cudaFuncAttributeMaxDynamicSharedMemorySize, SM2_64);
    cudaFuncSetAttribute((const void*)gemm2_kernel<96>,  cudaFuncAttributeMaxDynamicSharedMemorySize, SM2_96);

    const int NB  = (N_NODES + 127) / 128;             // 782
    const int GB  = (N_NODES * 32 + 255) / 256;        // 12500 (warp per node)

    // ---- dtype normalize + CSR build (runs every replay; ~15 us) ----
    detect_kernel<<<1, 256>>>(ei, (long long)N_EDGES, N_NODES, f_ei);     // safe: covers int32 case
    detect_kernel<<<1, 256>>>(batch, (long long)N_NODES / 2, N_GRAPHS, f_b);
    cudaMemsetAsync(deg, 0, N_NODES * sizeof(int), 0);
    convert_hist_kernel<<<(N_EDGES + 255) / 256, 256>>>(ei, f_ei, src, dst, deg);
    convert_batch_kernel<<<(N_NODES + 255) / 256, 256>>>(batch, f_b, b32);
    partials_kernel<<<NB_SCAN, SCAN_BS>>>(deg, part);
    scan_partials_kernel<<<1, 512>>>(part, poff);
    rowptr_kernel<<<NB_SCAN, SCAN_BS>>>(deg, poff, rowptr, cursor);
    fill_kernel<<<(N_EDGES + 255) / 256, 256>>>(src, dst, cursor, colv);

    // ---- layer 0 (K=128) ----
    gemm1_kernel<128><<<NB, 128, SM1_128>>>(x, P[0], y);
    gather_kernel<<<GB, 256>>>(y, rowptr, colv, aggr);
    gemm2_kernel<64><<<NB, 128, SM2_64>>>(aggr, P[1], P[2], P[3], P[4], P[5], P[6], P[7], a);

    // ---- layer 1 ----
    gemm1_kernel<64><<<NB, 128, SM1_64>>>(a, P[8], y);
    gather_kernel<<<GB, 256>>>(y, rowptr, colv, aggr);
    gemm2_kernel<64><<<NB, 128, SM2_64>>>(aggr, P[9], P[10], P[11], P[12], P[13], P[14], P[15], a);

    // ---- layer 2 (out=96) ----
    gemm1_kernel<64><<<NB, 128, SM1_64>>>(a, P[16], y);
    gather_kernel<<<GB, 256>>>(y, rowptr, colv, aggr);
    gemm2_kernel<96><<<NB, 128, SM2_96>>>(aggr, P[17], P[18], P[19], P[20], P[21], P[22], P[23], f);

    // ---- mean pool ----
    cudaMemsetAsync(sums, 0, N_GRAPHS * 96 * sizeof(float), 0);
    cudaMemsetAsync(cnts, 0, N_GRAPHS * sizeof(int), 0);
    pool_kernel<<<(N_NODES + PB_NODES - 1) / PB_NODES, 96>>>(f, b32, sums, cnts);
    finalize_kernel<<<(N_GRAPHS * 96 + 255) / 256, 256>>>(sums, cnts, (float*)d_out);
}

// round 5
// speedup vs baseline: 1.9361x; 1.5703x over previous
#include <cuda_runtime.h>
#include <cuda_bf16.h>
#include <cstdint>

#define N_NODES 100000
#define N_EDGES 600000
#define N_GRAPHS 64
#define BN_EPS 1e-5f
#define SCAN_BS 256
#define NB_SCAN ((N_NODES + SCAN_BS - 1) / SCAN_BS)   // 391

// ================= helpers =================
__device__ __forceinline__ uint32_t smem_u32(const void* p) {
    uint32_t a;
    asm("{ .reg .u64 t; cvta.to.shared.u64 t, %1; cvt.u32.u64 %0, t; }" : "=r"(a) : "l"(p));
    return a;
}
__device__ __forceinline__ void sts32(uint32_t addr, uint32_t v) {
    asm volatile("st.shared.b32 [%0], %1;" :: "r"(addr), "r"(v));
}
__device__ __forceinline__ void ldsm4(uint32_t r[4], uint32_t a) {
    asm volatile("ldmatrix.sync.aligned.m8n8.x4.shared.b16 {%0,%1,%2,%3}, [%4];"
                 : "=r"(r[0]), "=r"(r[1]), "=r"(r[2]), "=r"(r[3]) : "r"(a));
}
__device__ __forceinline__ void ldsm2(uint32_t r[2], uint32_t a) {
    asm volatile("ldmatrix.sync.aligned.m8n8.x2.shared.b16 {%0,%1}, [%2];"
                 : "=r"(r[0]), "=r"(r[1]) : "r"(a));
}
__device__ __forceinline__ void mma_bf16(float c[4], const uint32_t a[4], const uint32_t b[2]) {
    asm volatile("mma.sync.aligned.m16n8k16.row.col.f32.bf16.bf16.f32 "
                 "{%0,%1,%2,%3}, {%4,%5,%6,%7}, {%8,%9}, {%0,%1,%2,%3};"
                 : "+f"(c[0]), "+f"(c[1]), "+f"(c[2]), "+f"(c[3])
                 : "r"(a[0]), "r"(a[1]), "r"(a[2]), "r"(a[3]), "r"(b[0]), "r"(b[1]));
}
__device__ __forceinline__ void split2(float a, float b, uint32_t& hi, uint32_t& lo) {
    __nv_bfloat16 ha = __float2bfloat16(a), hb = __float2bfloat16(b);
    __nv_bfloat16 la = __float2bfloat16(a - __bfloat162float(ha));
    __nv_bfloat16 lb = __float2bfloat16(b - __bfloat162float(hb));
    __nv_bfloat162 H; H.x = ha; H.y = hb;
    __nv_bfloat162 L; L.x = la; L.y = lb;
    hi = *(uint32_t*)&H; lo = *(uint32_t*)&L;
}

// ================= scratch =================
__device__ float g_y[(size_t)N_NODES * 64];
__device__ float g_aggr[(size_t)N_NODES * 64];
__device__ float g_a[(size_t)N_NODES * 64];
__device__ float g_f[(size_t)N_NODES * 96];
__device__ float g_sums[N_GRAPHS * 96];
__device__ int   g_cnts[N_GRAPHS];
__device__ int   g_src[N_EDGES];
__device__ int   g_dst[N_EDGES];
__device__ int   g_batch32[N_NODES];
__device__ int   g_deg[N_NODES];
__device__ int   g_rowptr[N_NODES + 1];
__device__ int   g_cursor[N_NODES];
__device__ int   g_col[N_EDGES];
__device__ int   g_part[NB_SCAN];
__device__ int   g_poff[NB_SCAN];
__device__ int   g_is64_ei;
__device__ int   g_is64_b;
#define WTOT 30720
__device__ __nv_bfloat16 g_whi[WTOT];
__device__ __nv_bfloat16 g_wlo[WTOT];

// ================= dtype detect + convert + CSR =================
__global__ void detect_kernel(const void* p, long long n64_max, int maxval, int* flag) {
    __shared__ int ok;
    if (threadIdx.x == 0) ok = 1;
    __syncthreads();
    long long idx = (long long)threadIdx.x * (n64_max - 1) / 255;
    long long v = ((const long long*)p)[idx];
    if (v < 0 || v >= maxval) atomicAnd(&ok, 0);
    __syncthreads();
    if (threadIdx.x == 0) *flag = ok;
}
__global__ void convert_hist_kernel(const void* ei, const int* flag,
                                    int* __restrict__ src, int* __restrict__ dst,
                                    int* __restrict__ deg) {
    int i = blockIdx.x * blockDim.x + threadIdx.x;
    if (i >= N_EDGES) return;
    int s, d;
    if (*flag) {
        const long long* p = (const long long*)ei;
        s = (int)p[i]; d = (int)p[N_EDGES + i];
    } else {
        const int* p = (const int*)ei;
        s = p[i]; d = p[N_EDGES + i];
    }
    src[i] = s; dst[i] = d;
    atomicAdd(&deg[d], 1);
}
__global__ void convert_batch_kernel(const void* b, const int* flag, int* __restrict__ out) {
    int i = blockIdx.x * blockDim.x + threadIdx.x;
    if (i >= N_NODES) return;
    if (*flag) out[i] = (int)((const long long*)b)[i];
    else       out[i] = ((const int*)b)[i];
}
__global__ void partials_kernel(const int* __restrict__ deg, int* __restrict__ part) {
    __shared__ int sm[SCAN_BS];
    int i = blockIdx.x * SCAN_BS + threadIdx.x;
    sm[threadIdx.x] = (i < N_NODES) ? deg[i] : 0;
    __syncthreads();
#pragma unroll
    for (int s = SCAN_BS / 2; s > 0; s >>= 1) {
        if (threadIdx.x < s) sm[threadIdx.x] += sm[threadIdx.x + s];
        __syncthreads();
    }
    if (threadIdx.x == 0) part[blockIdx.x] = sm[0];
}
__global__ void scan_partials_kernel(const int* __restrict__ part, int* __restrict__ poff) {
    __shared__ int sm[NB_SCAN];
    int t = threadIdx.x;
    for (int i = t; i < NB_SCAN; i += blockDim.x) sm[i] = part[i];
    __syncthreads();
    if (t == 0) {
        int run = 0;
        for (int i = 0; i < NB_SCAN; i++) { int v = sm[i]; sm[i] = run; run += v; }
    }
    __syncthreads();
    for (int i = t; i < NB_SCAN; i += blockDim.x) poff[i] = sm[i];
}
__global__ void rowptr_kernel(const int* __restrict__ deg, const int* __restrict__ poff,
                              int* __restrict__ rowptr, int* __restrict__ cursor) {
    __shared__ int sm[SCAN_BS];
    int b = blockIdx.x, t = threadIdx.x;
    int i = b * SCAN_BS + t;
    int v = (i < N_NODES) ? deg[i] : 0;
    sm[t] = v;
    __syncthreads();
    for (int off = 1; off < SCAN_BS; off <<= 1) {
        int x = (t >= off) ? sm[t - off] : 0;
        __syncthreads();
        sm[t] += x;
        __syncthreads();
    }
    if (i < N_NODES) {
        int r = poff[b] + sm[t] - v;
        rowptr[i] = r;
        cursor[i] = r;
    }
    if (i == N_NODES - 1) rowptr[N_NODES] = poff[b] + sm[t];
}
__global__ void fill_kernel(const int* __restrict__ src, const int* __restrict__ dst,
                            int* __restrict__ cursor, int* __restrict__ col) {
    int e = blockIdx.x * blockDim.x + threadIdx.x;
    if (e >= N_EDGES) return;
    int d = dst[e];
    int pos = atomicAdd(&cursor[d], 1);
    col[pos] = src[e];
}

// ================= weight prep: transpose + bf16 hi/lo split ([N,K] row-major) =================
__global__ void wprep_kernel(const float* w10, const float* w20, const float* w11,
                             const float* w21, const float* w12, const float* w22,
                             __nv_bfloat16* __restrict__ whi, __nv_bfloat16* __restrict__ wlo) {
    int i = blockIdx.x * blockDim.x + threadIdx.x;
    if (i >= WTOT) return;
    const float* src; int K, N, off;
    if      (i < 8192)  { src = w10; K = 128; N = 64; off = 0; }
    else if (i < 12288) { src = w20; K = 64;  N = 64; off = 8192; }
    else if (i < 16384) { src = w11; K = 64;  N = 64; off = 12288; }
    else if (i < 20480) { src = w21; K = 64;  N = 64; off = 16384; }
    else if (i < 24576) { src = w12; K = 64;  N = 64; off = 20480; }
    else                { src = w22; K = 64;  N = 96; off = 24576; }
    int local = i - off;
    int n = local / K, k = local % K;
    float v = src[k * N + n];
    __nv_bfloat16 h = __float2bfloat16(v);
    whi[i] = h;
    wlo[i] = __float2bfloat16(v - __bfloat162float(h));
}

// ================= HMMA GEMM (mma.sync bf16 3-split) =================
// OUT[128tile, N] = f(A) @ W^T, A = X (optionally ReLU(X + b1)), W = [N,K] bf16 hi/lo
// epilogue: optional BN+ReLU
template <int K, int N, bool INREL, bool OUTBN>
__global__ __launch_bounds__(128) void hgemm(const float* __restrict__ X,
                                             const float* __restrict__ b1,
                                             const __nv_bfloat16* __restrict__ Whi,
                                             const __nv_bfloat16* __restrict__ Wlo,
                                             const float* __restrict__ b2,
                                             const float* __restrict__ bng,
                                             const float* __restrict__ bnb,
                                             const float* __restrict__ bnm,
                                             const float* __restrict__ bnv,
                                             float* __restrict__ OUT) {
    constexpr int SP  = K + 8;       // padded stride (elements)
    constexpr int SPB = SP * 2;      // bytes (multiple of 16)
    constexpr int NT  = N / 8;       // n-tiles
    extern __shared__ char dsm[];
    uint32_t aHi = smem_u32(dsm);
    uint32_t aLo = aHi + 128 * SPB;
    uint32_t wHi = aLo + 128 * SPB;
    uint32_t wLo = wHi + N * SPB;
    __shared__ float sScale[128];
    __shared__ float sShift[128];

    const int tid = threadIdx.x, warp = tid >> 5, lane = tid & 31;
    const int base = blockIdx.x * 128;

    if (OUTBN && tid < N) {
        float s = bng[tid] * rsqrtf(bnv[tid] + BN_EPS);
        sScale[tid] = s;
        sShift[tid] = (b2[tid] - bnm[tid]) * s + bnb[tid];
    }

    // stage W: [N,K] bf16 -> padded smem rows
    for (int i = tid; i < N * K / 2; i += 128) {
        int byte = i * 4;
        int row = byte / (K * 2), kb = byte - row * (K * 2);
        uint32_t off = (uint32_t)row * SPB + kb;
        sts32(wHi + off, ((const uint32_t*)Whi)[i]);
        sts32(wLo + off, ((const uint32_t*)Wlo)[i]);
    }
    // stage A: f32 -> bf16 hi/lo (optional bias+relu), padded rows
    constexpr int N4 = K / 4;
    for (int i = tid; i < 128 * N4; i += 128) {
        int row = i / N4, c4 = i - row * N4, col = c4 * 4;
        float4 v = make_float4(0.f, 0.f, 0.f, 0.f);
        if (base + row < N_NODES) {
            v = ((const float4*)X)[(size_t)(base + row) * N4 + c4];
            if (INREL) {
                v.x = fmaxf(v.x + __ldg(b1 + col + 0), 0.f);
                v.y = fmaxf(v.y + __ldg(b1 + col + 1), 0.f);
                v.z = fmaxf(v.z + __ldg(b1 + col + 2), 0.f);
                v.w = fmaxf(v.w + __ldg(b1 + col + 3), 0.f);
            }
        }
        uint32_t h01, l01, h23, l23;
        split2(v.x, v.y, h01, l01);
        split2(v.z, v.w, h23, l23);
        uint32_t off = (uint32_t)row * SPB + col * 2;
        sts32(aHi + off, h01); sts32(aHi + off + 4, h23);
        sts32(aLo + off, l01); sts32(aLo + off + 4, l23);
    }
    __syncthreads();

    float acc[2][NT][4];
#pragma unroll
    for (int t = 0; t < 2; t++)
#pragma unroll
        for (int n = 0; n < NT; n++)
#pragma unroll
            for (int j = 0; j < 4; j++) acc[t][n][j] = 0.f;

    // per-lane ldmatrix addresses
    const int arow  = warp * 32 + (lane & 15);
    const int ahalf = lane >> 4;             // 0/1 -> k half
    const int brow  = lane & 7;
    const int bhalf = (lane >> 3) & 1;

#pragma unroll
    for (int s = 0; s < 3; s++) {
        uint32_t Ab = (s == 2) ? aLo : aHi;
        uint32_t Wb = (s == 1) ? wLo : wHi;
#pragma unroll
        for (int k16 = 0; k16 < K / 16; k16++) {
            uint32_t kbyte = (uint32_t)(k16 * 16) * 2;
            uint32_t af0[4], af1[4];
            ldsm4(af0, Ab + (uint32_t)arow * SPB + kbyte + ahalf * 16);
            ldsm4(af1, Ab + (uint32_t)(arow + 16) * SPB + kbyte + ahalf * 16);
#pragma unroll
            for (int n8 = 0; n8 < NT; n8++) {
                uint32_t bf[2];
                ldsm2(bf, Wb + (uint32_t)(n8 * 8 + brow) * SPB + kbyte + bhalf * 16);
                mma_bf16(acc[0][n8], af0, bf);
                mma_bf16(acc[1][n8], af1, bf);
            }
        }
    }

    // epilogue
    const int r_in_warp = lane >> 2;        // 0..7
    const int cpair = (lane & 3) * 2;
#pragma unroll
    for (int t = 0; t < 2; t++) {
        int row0 = base + warp * 32 + t * 16 + r_in_warp;
        int row1 = row0 + 8;
#pragma unroll
        for (int n8 = 0; n8 < NT; n8++) {
            int col = n8 * 8 + cpair;
            float c0 = acc[t][n8][0], c1 = acc[t][n8][1];
            float c2 = acc[t][n8][2], c3 = acc[t][n8][3];
            if (OUTBN) {
                c0 = fmaxf(c0 * sScale[col] + sShift[col], 0.f);
                c1 = fmaxf(c1 * sScale[col + 1] + sShift[col + 1], 0.f);
                c2 = fmaxf(c2 * sScale[col] + sShift[col], 0.f);
                c3 = fmaxf(c3 * sScale[col + 1] + sShift[col + 1], 0.f);
            }
            if (row0 < N_NODES) *(float2*)(OUT + (size_t)row0 * N + col) = make_float2(c0, c1);
            if (row1 < N_NODES) *(float2*)(OUT + (size_t)row1 * N + col) = make_float2(c2, c3);
        }
    }
}

// ================= gather: AG[i] = y[i] + sum_{CSR row i} y[col[e]] =================
__global__ __launch_bounds__(256) void gather_kernel(const float* __restrict__ Y,
                                                     const int* __restrict__ rowptr,
                                                     const int* __restrict__ col,
                                                     float* __restrict__ AG) {
    int w = (blockIdx.x * blockDim.x + threadIdx.x) >> 5;
    int lane = threadIdx.x & 31;
    if (w >= N_NODES) return;
    const float2* y2 = (const float2*)Y;
    int r0 = rowptr[w], r1 = rowptr[w + 1];
    float2 acc = y2[(size_t)w * 32 + lane];
    int e = r0;
    for (; e + 1 < r1; e += 2) {
        int s0 = col[e], s1 = col[e + 1];
        float2 a = y2[(size_t)s0 * 32 + lane];
        float2 b = y2[(size_t)s1 * 32 + lane];
        acc.x += a.x + b.x;
        acc.y += a.y + b.y;
    }
    if (e < r1) {
        int s = col[e];
        float2 a = y2[(size_t)s * 32 + lane];
        acc.x += a.x;
        acc.y += a.y;
    }
    ((float2*)AG)[(size_t)w * 32 + lane] = acc;
}

// ================= pool =================
#define PB_NODES 64
__global__ void pool_kernel(const float* __restrict__ F, const int* __restrict__ batch,
                            float* __restrict__ sums, int* __restrict__ cnts) {
    __shared__ int sb[PB_NODES];
    const int start = blockIdx.x * PB_NODES;
    const int nn = min(PB_NODES, N_NODES - start);
    const int tid = threadIdx.x;   // 96
    if (tid < nn) sb[tid] = batch[start + tid];
    __syncthreads();
    if (tid == 0) {
        int cur = sb[0], c = 0;
        for (int n = 0; n < nn; n++) {
            int g = sb[n];
            if (g != cur) { atomicAdd(&cnts[cur], c); cur = g; c = 0; }
            c++;
        }
        atomicAdd(&cnts[cur], c);
    }
    int cur = sb[0];
    float acc = 0.f;
    for (int n = 0; n < nn; n++) {
        int g = sb[n];
        float v = F[(size_t)(start + n) * 96 + tid];
        if (g != cur) { atomicAdd(&sums[cur * 96 + tid], acc); acc = 0.f; cur = g; }
        acc += v;
    }
    atomicAdd(&sums[cur * 96 + tid], acc);
}
__global__ void finalize_kernel(const float* __restrict__ sums, const int* __restrict__ cnts,
                                float* __restrict__ out) {
    int i = blockIdx.x * blockDim.x + threadIdx.x;
    if (i >= N_GRAPHS * 96) return;
    float c = fmaxf((float)cnts[i / 96], 1.f);
    out[i] = sums[i] / c;
}

// ================= launch =================
extern "C" void kernel_launch(void* const* d_in, const int* in_sizes, int n_in,
                              void* d_out, int out_size) {
    const float* x     = (const float*)d_in[0];
    const void*  ei    = d_in[1];
    const void*  batch = d_in[2];
    const float* P[24];
    for (int i = 0; i < 24; i++) P[i] = (const float*)d_in[3 + i];

    float *y, *aggr, *a, *f, *sums;
    int *cnts, *src, *dst, *b32, *f_ei, *f_b;
    int *deg, *rowptr, *cursor, *colv, *part, *poff;
    __nv_bfloat16 *whi, *wlo;
    cudaGetSymbolAddress((void**)&y,      g_y);
    cudaGetSymbolAddress((void**)&aggr,   g_aggr);
    cudaGetSymbolAddress((void**)&a,      g_a);
    cudaGetSymbolAddress((void**)&f,      g_f);
    cudaGetSymbolAddress((void**)&sums,   g_sums);
    cudaGetSymbolAddress((void**)&cnts,   g_cnts);
    cudaGetSymbolAddress((void**)&src,    g_src);
    cudaGetSymbolAddress((void**)&dst,    g_dst);
    cudaGetSymbolAddress((void**)&b32,    g_batch32);
    cudaGetSymbolAddress((void**)&f_ei,   g_is64_ei);
    cudaGetSymbolAddress((void**)&f_b,    g_is64_b);
    cudaGetSymbolAddress((void**)&deg,    g_deg);
    cudaGetSymbolAddress((void**)&rowptr, g_rowptr);
    cudaGetSymbolAddress((void**)&cursor, g_cursor);
    cudaGetSymbolAddress((void**)&colv,   g_col);
    cudaGetSymbolAddress((void**)&part,   g_part);
    cudaGetSymbolAddress((void**)&poff,   g_poff);
    cudaGetSymbolAddress((void**)&whi,    g_whi);
    cudaGetSymbolAddress((void**)&wlo,    g_wlo);

    // smem sizes: (128 rows A hi+lo + N rows W hi+lo) * (K+8)*2 bytes
    const int SM_G1_128 = (256 + 128) * (136 * 2);   // 104448
    const int SM_G1_64  = (256 + 128) * (72 * 2);    // 55296
    const int SM_G2_64  = SM_G1_64;
    const int SM_G2_96  = (256 + 192) * (72 * 2);    // 64512
    cudaFuncSetAttribute((const void*)hgemm<128, 64, false, false>, cudaFuncAttributeMaxDynamicSharedMemorySize, SM_G1_128);
    cudaFuncSetAttribute((const void*)hgemm<64, 64, false, false>,  cudaFuncAttributeMaxDynamicSharedMemorySize, SM_G1_64);
    cudaFuncSetAttribute((const void*)hgemm<64, 64, true, true>,    cudaFuncAttributeMaxDynamicSharedMemorySize, SM_G2_64);
    cudaFuncSetAttribute((const void*)hgemm<64, 96, true, true>,    cudaFuncAttributeMaxDynamicSharedMemorySize, SM_G2_96);

    const int NB = (N_NODES + 127) / 128;          // 782
    const int GB = (N_NODES * 32 + 255) / 256;     // 12500

    // ---- dtype normalize + CSR build ----
    detect_kernel<<<1, 256>>>(ei, (long long)N_EDGES, N_NODES, f_ei);
    detect_kernel<<<1, 256>>>(batch, (long long)N_NODES / 2, N_GRAPHS, f_b);
    cudaMemsetAsync(deg, 0, N_NODES * sizeof(int), 0);
    convert_hist_kernel<<<(N_EDGES + 255) / 256, 256>>>(ei, f_ei, src, dst, deg);
    convert_batch_kernel<<<(N_NODES + 255) / 256, 256>>>(batch, f_b, b32);
    partials_kernel<<<NB_SCAN, SCAN_BS>>>(deg, part);
    scan_partials_kernel<<<1, 512>>>(part, poff);
    rowptr_kernel<<<NB_SCAN, SCAN_BS>>>(deg, poff, rowptr, cursor);
    fill_kernel<<<(N_EDGES + 255) / 256, 256>>>(src, dst, cursor, colv);

    // ---- weight prep (transpose + bf16 split) ----
    wprep_kernel<<<(WTOT + 255) / 256, 256>>>(P[0], P[2], P[8], P[10], P[16], P[18], whi, wlo);
    const int O_W10 = 0, O_W20 = 8192, O_W11 = 12288, O_W21 = 16384, O_W12 = 20480, O_W22 = 24576;

    // ---- layer 0 (K=128) ----
    hgemm<128, 64, false, false><<<NB, 128, SM_G1_128>>>(x, nullptr, whi + O_W10, wlo + O_W10,
                                                         nullptr, nullptr, nullptr, nullptr, nullptr, y);
    gather_kernel<<<GB, 256>>>(y, rowptr, colv, aggr);
    hgemm<64, 64, true, true><<<NB, 128, SM_G2_64>>>(aggr, P[1], whi + O_W20, wlo + O_W20,
                                                     P[3], P[4], P[5], P[6], P[7], a);
    // ---- layer 1 ----
    hgemm<64, 64, false, false><<<NB, 128, SM_G1_64>>>(a, nullptr, whi + O_W11, wlo + O_W11,
                                                       nullptr, nullptr, nullptr, nullptr, nullptr, y);
    gather_kernel<<<GB, 256>>>(y, rowptr, colv, aggr);
    hgemm<64, 64, true, true><<<NB, 128, SM_G2_64>>>(aggr, P[9], whi + O_W21, wlo + O_W21,
                                                     P[11], P[12], P[13], P[14], P[15], a);
    // ---- layer 2 (out=96) ----
    hgemm<64, 64, false, false><<<NB, 128, SM_G1_64>>>(a, nullptr, whi + O_W12, wlo + O_W12,
                                                       nullptr, nullptr, nullptr, nullptr, nullptr, y);
    gather_kernel<<<GB, 256>>>(y, rowptr, colv, aggr);
    hgemm<64, 96, true, true><<<NB, 128, SM_G2_96>>>(aggr, P[17], whi + O_W22, wlo + O_W22,
                                                     P[19], P[20], P[21], P[22], P[23], f);

    // ---- mean pool ----
    cudaMemsetAsync(sums, 0, N_GRAPHS * 96 * sizeof(float), 0);
    cudaMemsetAsync(cnts, 0, N_GRAPHS * sizeof(int), 0);
    pool_kernel<<<(N_NODES + PB_NODES - 1) / PB_NODES, 96>>>(f, b32, sums, cnts);
    finalize_kernel<<<(N_GRAPHS * 96 + 255) / 256, 256>>>(sums, cnts, (float*)d_out);
}